// round 1
// baseline (speedup 1.0000x reference)
#include <cuda_runtime.h>
#include <math.h>

#define NN   32
#define CCH  64
#define TTT  400
#define VVV  27
#define VP   28
#define SSS  2
#define TVC  (TTT*VVV)      // 10800
#define CTV  (CCH*TVC)      // 691200
#define LEAK 0.1f
#define EPSB 1e-5f

#define KSP  25             // split-K for att
#define TB   16             // t per att block

// scratch (static device globals — allocation-free rule)
__device__ float g_qk[NN*CCH*TTT*VVV];          // 88.5 MB
__device__ float g_y3[NN*CCH*TTT*VVV];          // 88.5 MB
__device__ float g_att_part[KSP*NN*SSS*VVV*VVV];
__device__ float g_att[NN*SSS*VVV*VVV];

// ---------------------------------------------------------------------------
// K1: qk[n,oc,t,v] = sum_c W_in[oc,c]*(x[n,c,t,v]+pe[c,t,v]) + b_in[oc]
// block (64 oc, 4 t), grid (100, 32)
// ---------------------------------------------------------------------------
__global__ __launch_bounds__(256) void k1_qk(const float* __restrict__ x,
                                             const float* __restrict__ pe,
                                             const float* __restrict__ Wi,
                                             const float* __restrict__ bi) {
    __shared__ float sW[64*64];       // [c][oc]
    __shared__ float sY[4*64*VP];     // [tq][c][v], padded
    int n = blockIdx.y, t0 = blockIdx.x*4;
    int tid = threadIdx.y*64 + threadIdx.x;
    for (int i = tid; i < 4096; i += 256) { int o = i>>6, c = i&63; sW[c*64+o] = Wi[i]; }
    for (int i = tid; i < 4*64*27; i += 256) {
        int v = i%27; int c = (i/27)&63; int tq = i/1728;
        int idx = (c*TTT + t0+tq)*27 + v;
        sY[(tq*64+c)*VP + v] = x[n*CTV + idx] + pe[idx];
    }
    { int tq = tid>>6, c = tid&63; sY[(tq*64+c)*VP + 27] = 0.f; }
    __syncthreads();
    int oc = threadIdx.x, tq = threadIdx.y;
    float acc[28];
#pragma unroll
    for (int j = 0; j < 28; j++) acc[j] = 0.f;
    const float* yb = &sY[tq*64*VP];
    for (int c = 0; c < 64; c++) {
        float w = sW[c*64 + oc];
        const float4* y4 = (const float4*)&yb[c*VP];
#pragma unroll
        for (int j = 0; j < 7; j++) {
            float4 q = y4[j];
            acc[4*j+0] += w*q.x; acc[4*j+1] += w*q.y;
            acc[4*j+2] += w*q.z; acc[4*j+3] += w*q.w;
        }
    }
    float b = bi[oc];
    float* dst = &g_qk[n*CTV + oc*TVC + (t0+tq)*27];
#pragma unroll
    for (int v = 0; v < 27; v++) dst[v] = acc[v] + b;
}

// ---------------------------------------------------------------------------
// K2: partial att[n,s,u,v] = sum over (c=16, t-range of 16) q*k
// grid (25,2,32), block 96 (81 active, each owns 3x3 (u,v) register tile)
// ---------------------------------------------------------------------------
__global__ __launch_bounds__(96) void k2_part() {
    int ksp = blockIdx.x, s = blockIdx.y, n = blockIdx.z;
    __shared__ float sq[16*8*27], sk[16*8*27];
    int tid = threadIdx.x;
    int tu = (tid < 81) ? tid/9 : 0, tv = (tid < 81) ? tid%9 : 0;
    int u0 = 3*tu, v0 = 3*tv;
    float a00=0,a01=0,a02=0,a10=0,a11=0,a12=0,a20=0,a21=0,a22=0;
    for (int ch = 0; ch < 2; ch++) {
        int tbase = ksp*TB + ch*8;
        for (int i = tid; i < 3456; i += 96) {
            int u = i%27; int t8 = (i/27)&7; int c = i/216;
            int gq = n*CTV + (s*16 + c)*TVC + (tbase + t8)*27 + u;
            sq[i] = g_qk[gq];
            sk[i] = g_qk[gq + 32*TVC];
        }
        __syncthreads();
        if (tid < 81) {
#pragma unroll
            for (int c = 0; c < 16; c++) {
#pragma unroll
                for (int t8 = 0; t8 < 8; t8++) {
                    const float* qr = &sq[(c*8+t8)*27];
                    const float* kr = &sk[(c*8+t8)*27];
                    float q0=qr[u0],q1=qr[u0+1],q2=qr[u0+2];
                    float k0=kr[v0],k1=kr[v0+1],k2=kr[v0+2];
                    a00+=q0*k0; a01+=q0*k1; a02+=q0*k2;
                    a10+=q1*k0; a11+=q1*k1; a12+=q1*k2;
                    a20+=q2*k0; a21+=q2*k1; a22+=q2*k2;
                }
            }
        }
        __syncthreads();
    }
    if (tid < 81) {
        float* dst = &g_att_part[((ksp*NN + n)*SSS + s)*729];
        dst[(u0+0)*27+v0+0]=a00; dst[(u0+0)*27+v0+1]=a01; dst[(u0+0)*27+v0+2]=a02;
        dst[(u0+1)*27+v0+0]=a10; dst[(u0+1)*27+v0+1]=a11; dst[(u0+1)*27+v0+2]=a12;
        dst[(u0+2)*27+v0+0]=a20; dst[(u0+2)*27+v0+1]=a21; dst[(u0+2)*27+v0+2]=a22;
    }
}

__global__ void k2_fin(const float* __restrict__ alphas, const float* __restrict__ att0) {
    int i = blockIdx.x*256 + threadIdx.x;
    if (i >= NN*SSS*729) return;
    float acc = 0.f;
#pragma unroll
    for (int sp = 0; sp < KSP; sp++) acc += g_att_part[sp*(NN*SSS*729) + i];
    int r = i % (SSS*729); int s = r/729; int uv = r%729;
    g_att[i] = tanhf(acc * (1.f/6400.f)) * alphas[s] + att0[s*729 + uv];
}

// ---------------------------------------------------------------------------
// K3: fused  P=W_out@x, acc=att-apply(P), y2=lrelu(x+BN(acc+b)), 
//            yf=W_ff@y2, y3=lrelu(x+BN(yf)); write y3
// block (64 oc, 4 t), grid (100, 32); dynamic smem 112.5 KB
// ---------------------------------------------------------------------------
#define K3_SMEM_FLOATS (8192 + 4096 + 2*27*VP + 4*64*VP + 4*64*VP)
__global__ __launch_bounds__(256) void k3_fused(
    const float* __restrict__ x,
    const float* __restrict__ Wo, const float* __restrict__ bo,
    const float* __restrict__ go, const float* __restrict__ beo,
    const float* __restrict__ mo, const float* __restrict__ vo,
    const float* __restrict__ Wf, const float* __restrict__ bf,
    const float* __restrict__ gf, const float* __restrict__ bef,
    const float* __restrict__ mf, const float* __restrict__ vf) {
    extern __shared__ float sm[];
    float* sWo  = sm;                 // [k=128][o=64]
    float* sWf  = sm + 8192;          // [c=64][o=64]
    float* sAtt = sm + 12288;         // [s][u][VP]
    float* sX   = sm + 12288 + 2*27*VP;           // [tq][c][VP]
    float* sY2  = sm + 12288 + 2*27*VP + 4*64*VP; // [tq][c][VP]
    int n = blockIdx.y, t0 = blockIdx.x*4;
    int tid = threadIdx.y*64 + threadIdx.x;
    for (int i = tid; i < 8192; i += 256) { int o = i>>7, k = i&127; sWo[k*64+o] = Wo[i]; }
    for (int i = tid; i < 4096; i += 256) { int o = i>>6, c = i&63;  sWf[c*64+o] = Wf[i]; }
    for (int i = tid; i < 1458; i += 256) {
        int s = i/729, r = i%729; int u = r/27, v = r%27;
        sAtt[(s*27+u)*VP + v] = g_att[(n*SSS+s)*729 + r];
    }
    if (tid < 54) { int s = tid/27, u = tid%27; sAtt[(s*27+u)*VP + 27] = 0.f; }
    for (int i = tid; i < 4*64*27; i += 256) {
        int v = i%27; int c = (i/27)&63; int tq = i/1728;
        sX[(tq*64+c)*VP + v] = x[n*CTV + c*TVC + (t0+tq)*27 + v];
    }
    { int tq = tid>>6, c = tid&63; sX[(tq*64+c)*VP + 27] = 0.f; }
    __syncthreads();

    int oc = threadIdx.x, tq = threadIdx.y;
    const float* xb = &sX[tq*64*VP];
    float acc[28];
#pragma unroll
    for (int j = 0; j < 28; j++) acc[j] = 0.f;
#pragma unroll
    for (int s = 0; s < 2; s++) {
        float P[28];
#pragma unroll
        for (int j = 0; j < 28; j++) P[j] = 0.f;
        for (int c = 0; c < 64; c++) {
            float w = sWo[(s*64+c)*64 + oc];
            const float4* x4 = (const float4*)&xb[c*VP];
#pragma unroll
            for (int j = 0; j < 7; j++) {
                float4 q = x4[j];
                P[4*j+0] += w*q.x; P[4*j+1] += w*q.y;
                P[4*j+2] += w*q.z; P[4*j+3] += w*q.w;
            }
        }
#pragma unroll
        for (int u = 0; u < 27; u++) {
            float pu = P[u];
            const float4* a4 = (const float4*)&sAtt[(s*27+u)*VP];
#pragma unroll
            for (int j = 0; j < 7; j++) {
                float4 q = a4[j];
                acc[4*j+0] += pu*q.x; acc[4*j+1] += pu*q.y;
                acc[4*j+2] += pu*q.z; acc[4*j+3] += pu*q.w;
            }
        }
    }
    // y2 = lrelu(x + BN(acc + b_out))
    {
        float sc = go[oc]*rsqrtf(vo[oc]+EPSB);
        float bb = bo[oc], mm = mo[oc], be = beo[oc];
        float* y2b = &sY2[(tq*64+oc)*VP];
#pragma unroll
        for (int v = 0; v < 27; v++) {
            float y1 = acc[v] + bb;
            float t  = xb[oc*VP + v] + (y1 - mm)*sc + be;
            y2b[v] = (t >= 0.f) ? t : LEAK*t;
        }
        y2b[27] = 0.f;
    }
    __syncthreads();
    // yf = W_ff @ y2 ; y3 = lrelu(x + BN(yf + b_ff))
#pragma unroll
    for (int j = 0; j < 28; j++) acc[j] = 0.f;
    const float* y2t = &sY2[tq*64*VP];
    for (int c = 0; c < 64; c++) {
        float w = sWf[c*64 + oc];
        const float4* x4 = (const float4*)&y2t[c*VP];
#pragma unroll
        for (int j = 0; j < 7; j++) {
            float4 q = x4[j];
            acc[4*j+0] += w*q.x; acc[4*j+1] += w*q.y;
            acc[4*j+2] += w*q.z; acc[4*j+3] += w*q.w;
        }
    }
    {
        float sc = gf[oc]*rsqrtf(vf[oc]+EPSB);
        float bb = bf[oc], mm = mf[oc], be = bef[oc];
        float* dst = &g_y3[n*CTV + oc*TVC + (t0+tq)*27];
#pragma unroll
        for (int v = 0; v < 27; v++) {
            float yf = acc[v] + bb;
            float t  = xb[oc*VP + v] + (yf - mm)*sc + be;
            dst[v] = (t >= 0.f) ? t : LEAK*t;
        }
    }
}

// ---------------------------------------------------------------------------
// K4: z = BN(tconv3(y3) + b_t); out = lrelu(y3 + z)
// block (64 oc, 4 t), grid (100, 32); dynamic smem 92 KB
// ---------------------------------------------------------------------------
#define K4_SMEM_FLOATS (3*64*64 + 64*6*VP)
__global__ __launch_bounds__(256) void k4_tconv(
    const float* __restrict__ Wt, const float* __restrict__ bt,
    const float* __restrict__ gt, const float* __restrict__ bet,
    const float* __restrict__ mt, const float* __restrict__ vt,
    float* __restrict__ out) {
    extern __shared__ float sm[];
    float* sW = sm;            // [kt][i][o]
    float* sY = sm + 12288;    // [c][tt=6][VP]
    int n = blockIdx.y, t0 = blockIdx.x*4;
    int tid = threadIdx.y*64 + threadIdx.x;
    for (int i = tid; i < 12288; i += 256) {
        int o = i&63; int ii = (i>>6)&63; int kt = i>>12;
        sW[i] = Wt[(o*64 + ii)*3 + kt];
    }
    for (int i = tid; i < 64*6*27; i += 256) {
        int v = i%27; int tt = (i/27)%6; int c = i/162;
        int t = t0 - 1 + tt;
        sY[(c*6+tt)*VP + v] = (t >= 0 && t < TTT) ? g_y3[n*CTV + c*TVC + t*27 + v] : 0.f;
    }
    for (int i = tid; i < 64*6; i += 256) sY[i*VP + 27] = 0.f;
    __syncthreads();

    int oc = threadIdx.x, tq = threadIdx.y;
    float bb = bt[oc];
    float acc[28];
#pragma unroll
    for (int j = 0; j < 28; j++) acc[j] = bb;
#pragma unroll
    for (int dt = 0; dt < 3; dt++) {
        for (int c = 0; c < 64; c++) {
            float w = sW[(dt*64+c)*64 + oc];
            const float4* y4 = (const float4*)&sY[(c*6 + tq + dt)*VP];
#pragma unroll
            for (int j = 0; j < 7; j++) {
                float4 q = y4[j];
                acc[4*j+0] += w*q.x; acc[4*j+1] += w*q.y;
                acc[4*j+2] += w*q.z; acc[4*j+3] += w*q.w;
            }
        }
    }
    float sc = gt[oc]*rsqrtf(vt[oc]+EPSB);
    float mm = mt[oc], be = bet[oc];
    float* dst = &out[n*CTV + oc*TVC + (t0+tq)*27];
    const float* yc = &sY[(oc*6 + tq + 1)*VP];
#pragma unroll
    for (int v = 0; v < 27; v++) {
        float z = (acc[v] - mm)*sc + be;
        float r = yc[v] + z;
        dst[v] = (r >= 0.f) ? r : LEAK*r;
    }
}

// ---------------------------------------------------------------------------
extern "C" void kernel_launch(void* const* d_in, const int* in_sizes, int n_in,
                              void* d_out, int out_size) {
    const float* x      = (const float*)d_in[0];
    const float* pe     = (const float*)d_in[1];
    const float* W_in   = (const float*)d_in[2];
    const float* b_in   = (const float*)d_in[3];
    const float* alphas = (const float*)d_in[4];
    const float* att0   = (const float*)d_in[5];
    const float* W_out  = (const float*)d_in[6];
    const float* b_out  = (const float*)d_in[7];
    const float* g_out  = (const float*)d_in[8];
    const float* be_out = (const float*)d_in[9];
    const float* m_out  = (const float*)d_in[10];
    const float* v_out  = (const float*)d_in[11];
    const float* W_ff   = (const float*)d_in[12];
    const float* b_ff   = (const float*)d_in[13];
    const float* g_ff   = (const float*)d_in[14];
    const float* be_ff  = (const float*)d_in[15];
    const float* m_ff   = (const float*)d_in[16];
    const float* v_ff   = (const float*)d_in[17];
    const float* W_t    = (const float*)d_in[18];
    const float* b_t    = (const float*)d_in[19];
    const float* g_t    = (const float*)d_in[20];
    const float* be_t   = (const float*)d_in[21];
    const float* m_t    = (const float*)d_in[22];
    const float* v_t    = (const float*)d_in[23];
    float* out = (float*)d_out;

    cudaFuncSetAttribute(k3_fused, cudaFuncAttributeMaxDynamicSharedMemorySize,
                         K3_SMEM_FLOATS*4);
    cudaFuncSetAttribute(k4_tconv, cudaFuncAttributeMaxDynamicSharedMemorySize,
                         K4_SMEM_FLOATS*4);

    dim3 blk(64, 4);
    k1_qk<<<dim3(100, 32), blk>>>(x, pe, W_in, b_in);
    k2_part<<<dim3(KSP, 2, 32), 96>>>();
    k2_fin<<<(NN*SSS*729 + 255)/256, 256>>>(alphas, att0);
    k3_fused<<<dim3(100, 32), blk, K3_SMEM_FLOATS*4>>>(
        x, W_out, b_out, g_out, be_out, m_out, v_out,
        W_ff, b_ff, g_ff, be_ff, m_ff, v_ff);
    k4_tconv<<<dim3(100, 32), blk, K4_SMEM_FLOATS*4>>>(
        W_t, b_t, g_t, be_t, m_t, v_t, out);
}

// round 2
// speedup vs baseline: 1.1198x; 1.1198x over previous
#include <cuda_runtime.h>
#include <math.h>

typedef unsigned long long u64;

#define NN   32
#define CCH  64
#define TTT  400
#define VVV  27
#define VP   28
#define SSS  2
#define TVC  (TTT*VVV)       // 10800
#define CTV  (CCH*TVC)       // 691200
#define TV28 (TTT*VP)        // 11200
#define CTV28 (CCH*TV28)     // 716800
#define LEAK 0.1f
#define EPSB 1e-5f
#define KSP  25
#define TB   16

// scratch (static device globals — allocation-free rule)
__device__ float g_buf1[NN*CCH*TV28];   // qk, later y2 (91.75 MB)
__device__ float g_buf2[NN*CCH*TV28];   // y3
__device__ float g_att_part[KSP*NN*SSS*VVV*VVV];
__device__ float g_att[NN*SSS*VVV*VVV];

// ---- packed fp32x2 helpers (Blackwell fma.rn.f32x2) ----
__device__ __forceinline__ u64 ffma2(u64 a, u64 b, u64 c) {
    u64 d; asm("fma.rn.f32x2 %0, %1, %2, %3;" : "=l"(d) : "l"(a), "l"(b), "l"(c));
    return d;
}
__device__ __forceinline__ u64 bcast2(float w) {
    u64 d; asm("mov.b64 %0, {%1, %1};" : "=l"(d) : "r"(__float_as_uint(w)));
    return d;
}
__device__ __forceinline__ float2 unpk(u64 a) {
    float2 r; asm("mov.b64 {%0, %1}, %2;" : "=f"(r.x), "=f"(r.y) : "l"(a));
    return r;
}

// ---------------------------------------------------------------------------
// K1: qk[n,oc,t,v] = sum_c W_in[oc,c]*(x[n,c,t,v]+pe[c,t,v]) + b_in[oc]
// writes padded (stride-28) g_buf1. block (64 oc, 4 t), grid (100, 32)
// ---------------------------------------------------------------------------
__global__ __launch_bounds__(256) void k1_qk(const float* __restrict__ x,
                                             const float* __restrict__ pe,
                                             const float* __restrict__ Wi,
                                             const float* __restrict__ bi) {
    __shared__ float sW[64*64];       // [c][oc]
    __shared__ float sY[4*64*VP];     // [tq][c][v], padded
    int n = blockIdx.y, t0 = blockIdx.x*4;
    int tid = threadIdx.y*64 + threadIdx.x;
    for (int i = tid; i < 4096; i += 256) { int o = i>>6, c = i&63; sW[c*64+o] = Wi[i]; }
    // coalesced float4 staging over contiguous 108-float (t,v) rows per c
    for (int i = tid; i < 1728; i += 256) {
        int c = i/27, j = i - c*27;
        int gbase = c*TVC + t0*27 + 4*j;
        float4 xv = *(const float4*)&x[n*CTV + gbase];
        float4 pv = *(const float4*)&pe[gbase];
        float vals[4] = {xv.x+pv.x, xv.y+pv.y, xv.z+pv.z, xv.w+pv.w};
        int pos = 4*j;
#pragma unroll
        for (int e = 0; e < 4; e++) {
            int p = pos + e, tq = p/27, v = p - tq*27;
            sY[(tq*64+c)*VP + v] = vals[e];
        }
    }
    { int tq = tid>>6, c = tid&63; sY[(tq*64+c)*VP + 27] = 0.f; }
    __syncthreads();
    int oc = threadIdx.x, tq = threadIdx.y;
    u64 acc[14];
#pragma unroll
    for (int j = 0; j < 14; j++) acc[j] = 0ull;
    const float* yb = &sY[tq*64*VP];
    for (int c = 0; c < 64; c++) {
        u64 w2 = bcast2(sW[c*64 + oc]);
        const ulonglong2* y2p = (const ulonglong2*)&yb[c*VP];
#pragma unroll
        for (int j = 0; j < 7; j++) {
            ulonglong2 q = y2p[j];
            acc[2*j]   = ffma2(w2, q.x, acc[2*j]);
            acc[2*j+1] = ffma2(w2, q.y, acc[2*j+1]);
        }
    }
    float b = bi[oc];
    float accf[28];
#pragma unroll
    for (int j = 0; j < 14; j++) { float2 p = unpk(acc[j]); accf[2*j] = p.x + b; accf[2*j+1] = p.y + b; }
    float4* dst = (float4*)&g_buf1[n*CTV28 + oc*TV28 + (t0+tq)*VP];
#pragma unroll
    for (int j = 0; j < 7; j++)
        dst[j] = make_float4(accf[4*j], accf[4*j+1], accf[4*j+2], accf[4*j+3]);
}

// ---------------------------------------------------------------------------
// K2: partial att[n,s,u,v] over (c=16, 16 t's). grid (25,2,32), block 96
// ---------------------------------------------------------------------------
__global__ __launch_bounds__(96) void k2_part() {
    int ksp = blockIdx.x, s = blockIdx.y, n = blockIdx.z;
    __shared__ float sq[16*8*27], sk[16*8*27];
    int tid = threadIdx.x;
    int tu = (tid < 81) ? tid/9 : 0, tv = (tid < 81) ? tid%9 : 0;
    int u0 = 3*tu, v0 = 3*tv;
    float a00=0,a01=0,a02=0,a10=0,a11=0,a12=0,a20=0,a21=0,a22=0;
    for (int ch = 0; ch < 2; ch++) {
        int tbase = ksp*TB + ch*8;
        for (int i = tid; i < 3456; i += 96) {
            int u = i%27; int t8 = (i/27)&7; int c = i/216;
            int gq = n*CTV28 + (s*16 + c)*TV28 + (tbase + t8)*VP + u;
            sq[i] = g_buf1[gq];
            sk[i] = g_buf1[gq + 32*TV28];
        }
        __syncthreads();
        if (tid < 81) {
#pragma unroll
            for (int c = 0; c < 16; c++) {
#pragma unroll
                for (int t8 = 0; t8 < 8; t8++) {
                    const float* qr = &sq[(c*8+t8)*27];
                    const float* kr = &sk[(c*8+t8)*27];
                    float q0=qr[u0],q1=qr[u0+1],q2=qr[u0+2];
                    float k0=kr[v0],k1=kr[v0+1],k2=kr[v0+2];
                    a00+=q0*k0; a01+=q0*k1; a02+=q0*k2;
                    a10+=q1*k0; a11+=q1*k1; a12+=q1*k2;
                    a20+=q2*k0; a21+=q2*k1; a22+=q2*k2;
                }
            }
        }
        __syncthreads();
    }
    if (tid < 81) {
        float* dst = &g_att_part[((ksp*NN + n)*SSS + s)*729];
        dst[(u0+0)*27+v0+0]=a00; dst[(u0+0)*27+v0+1]=a01; dst[(u0+0)*27+v0+2]=a02;
        dst[(u0+1)*27+v0+0]=a10; dst[(u0+1)*27+v0+1]=a11; dst[(u0+1)*27+v0+2]=a12;
        dst[(u0+2)*27+v0+0]=a20; dst[(u0+2)*27+v0+1]=a21; dst[(u0+2)*27+v0+2]=a22;
    }
}

__global__ void k2_fin(const float* __restrict__ alphas, const float* __restrict__ att0) {
    int i = blockIdx.x*256 + threadIdx.x;
    if (i >= NN*SSS*729) return;
    float acc = 0.f;
#pragma unroll
    for (int sp = 0; sp < KSP; sp++) acc += g_att_part[sp*(NN*SSS*729) + i];
    int r = i % (SSS*729); int s = r/729; int uv = r%729;
    g_att[i] = tanhf(acc * (1.f/6400.f)) * alphas[s] + att0[s*729 + uv];
}

// ---------------------------------------------------------------------------
// K3a: P=W_out@x (per s), acc=att-apply(P), y2=lrelu(x+BN(acc+b)) -> g_buf1
// smem 67.5 KB -> 3 CTAs/SM
// ---------------------------------------------------------------------------
#define K3A_SMEM_FLOATS (8192 + 2*27*VP + 4*64*VP)
__global__ __launch_bounds__(256,3) void k3a(
    const float* __restrict__ x,
    const float* __restrict__ Wo, const float* __restrict__ bo,
    const float* __restrict__ go, const float* __restrict__ beo,
    const float* __restrict__ mo, const float* __restrict__ vo) {
    extern __shared__ float sm[];
    float* sWo  = sm;                 // [s*64+c][oc]
    float* sAtt = sm + 8192;          // [s][u][VP]
    float* sX   = sm + 8192 + 2*27*VP; // [tq][c][VP]
    int n = blockIdx.y, t0 = blockIdx.x*4;
    int tid = threadIdx.y*64 + threadIdx.x;
    for (int i = tid; i < 8192; i += 256) { int o = i>>7, k = i&127; sWo[k*64+o] = Wo[i]; }
    for (int i = tid; i < 1458; i += 256) {
        int s = i/729, r = i%729; int u = r/27, v = r%27;
        sAtt[(s*27+u)*VP + v] = g_att[(n*SSS+s)*729 + r];
    }
    if (tid < 54) { int s = tid/27, u = tid%27; sAtt[(s*27+u)*VP + 27] = 0.f; }
    for (int i = tid; i < 1728; i += 256) {
        int c = i/27, j = i - c*27;
        float4 xv = *(const float4*)&x[n*CTV + c*TVC + t0*27 + 4*j];
        float vals[4] = {xv.x, xv.y, xv.z, xv.w};
        int pos = 4*j;
#pragma unroll
        for (int e = 0; e < 4; e++) {
            int p = pos + e, tq = p/27, v = p - tq*27;
            sX[(tq*64+c)*VP + v] = vals[e];
        }
    }
    { int tq = tid>>6, c = tid&63; sX[(tq*64+c)*VP + 27] = 0.f; }
    __syncthreads();

    int oc = threadIdx.x, tq = threadIdx.y;
    const float* xb = &sX[tq*64*VP];
    u64 acc[14];
#pragma unroll
    for (int j = 0; j < 14; j++) acc[j] = 0ull;
#pragma unroll
    for (int s = 0; s < 2; s++) {
        u64 P[14];
#pragma unroll
        for (int j = 0; j < 14; j++) P[j] = 0ull;
        for (int c = 0; c < 64; c++) {
            u64 w2 = bcast2(sWo[(s*64+c)*64 + oc]);
            const ulonglong2* x2p = (const ulonglong2*)&xb[c*VP];
#pragma unroll
            for (int j = 0; j < 7; j++) {
                ulonglong2 q = x2p[j];
                P[2*j]   = ffma2(w2, q.x, P[2*j]);
                P[2*j+1] = ffma2(w2, q.y, P[2*j+1]);
            }
        }
#pragma unroll
        for (int u = 0; u < 27; u++) {
            float2 pp = unpk(P[u>>1]);
            u64 pu2 = bcast2((u & 1) ? pp.y : pp.x);
            const ulonglong2* a2 = (const ulonglong2*)&sAtt[(s*27+u)*VP];
#pragma unroll
            for (int j = 0; j < 7; j++) {
                ulonglong2 q = a2[j];
                acc[2*j]   = ffma2(pu2, q.x, acc[2*j]);
                acc[2*j+1] = ffma2(pu2, q.y, acc[2*j+1]);
            }
        }
    }
    // y2 = lrelu(x + BN(acc + b_out)) -> padded g_buf1
    float sc = go[oc]*rsqrtf(vo[oc]+EPSB);
    float bb = bo[oc], mm = mo[oc], be = beo[oc];
    float accf[28];
#pragma unroll
    for (int j = 0; j < 14; j++) { float2 p = unpk(acc[j]); accf[2*j] = p.x; accf[2*j+1] = p.y; }
    float out28[28];
#pragma unroll
    for (int v = 0; v < 28; v++) {
        float y1 = accf[v] + bb;
        float t  = xb[oc*VP + v] + (y1 - mm)*sc + be;
        out28[v] = (t >= 0.f) ? t : LEAK*t;
    }
    float4* dst = (float4*)&g_buf1[n*CTV28 + oc*TV28 + (t0+tq)*VP];
#pragma unroll
    for (int j = 0; j < 7; j++)
        dst[j] = make_float4(out28[4*j], out28[4*j+1], out28[4*j+2], out28[4*j+3]);
}

// ---------------------------------------------------------------------------
// K3b: yf = W_ff @ y2 ; y3 = lrelu(x + BN(yf + b_ff)) -> g_buf2
// smem 72 KB -> 3 CTAs/SM
// ---------------------------------------------------------------------------
#define K3B_SMEM_FLOATS (4096 + 4*64*VP + 4*64*VP)
__global__ __launch_bounds__(256,3) void k3b(
    const float* __restrict__ x,
    const float* __restrict__ Wf, const float* __restrict__ bf,
    const float* __restrict__ gf, const float* __restrict__ bef,
    const float* __restrict__ mf, const float* __restrict__ vf) {
    extern __shared__ float sm[];
    float* sWf = sm;                  // [c][oc]
    float* sX  = sm + 4096;           // [tq][c][VP]
    float* sY2 = sm + 4096 + 4*64*VP; // [tq][c][VP]
    int n = blockIdx.y, t0 = blockIdx.x*4;
    int tid = threadIdx.y*64 + threadIdx.x;
    for (int i = tid; i < 4096; i += 256) { int o = i>>6, c = i&63; sWf[c*64+o] = Wf[i]; }
    for (int i = tid; i < 1728; i += 256) {
        int c = i/27, j = i - c*27;
        float4 xv = *(const float4*)&x[n*CTV + c*TVC + t0*27 + 4*j];
        float vals[4] = {xv.x, xv.y, xv.z, xv.w};
        int pos = 4*j;
#pragma unroll
        for (int e = 0; e < 4; e++) {
            int p = pos + e, tq = p/27, v = p - tq*27;
            sX[(tq*64+c)*VP + v] = vals[e];
        }
    }
    { int tq = tid>>6, c = tid&63; sX[(tq*64+c)*VP + 27] = 0.f; }
    // y2 staging: padded global -> padded smem, pure float4 copies
    for (int i = tid; i < 1792; i += 256) {
        int tq = i/448, r = i - tq*448; int c = r/7, j = r - c*7;
        ((float4*)&sY2[(tq*64+c)*VP])[j] =
            ((const float4*)&g_buf1[n*CTV28 + c*TV28 + (t0+tq)*VP])[j];
    }
    __syncthreads();

    int oc = threadIdx.x, tq = threadIdx.y;
    const float* xb  = &sX[tq*64*VP];
    const float* y2t = &sY2[tq*64*VP];
    u64 acc[14];
#pragma unroll
    for (int j = 0; j < 14; j++) acc[j] = 0ull;
    for (int c = 0; c < 64; c++) {
        u64 w2 = bcast2(sWf[c*64 + oc]);
        const ulonglong2* x2p = (const ulonglong2*)&y2t[c*VP];
#pragma unroll
        for (int j = 0; j < 7; j++) {
            ulonglong2 q = x2p[j];
            acc[2*j]   = ffma2(w2, q.x, acc[2*j]);
            acc[2*j+1] = ffma2(w2, q.y, acc[2*j+1]);
        }
    }
    float sc = gf[oc]*rsqrtf(vf[oc]+EPSB);
    float bb = bf[oc], mm = mf[oc], be = bef[oc];
    float accf[28];
#pragma unroll
    for (int j = 0; j < 14; j++) { float2 p = unpk(acc[j]); accf[2*j] = p.x; accf[2*j+1] = p.y; }
    float out28[28];
#pragma unroll
    for (int v = 0; v < 28; v++) {
        float yf = accf[v] + bb;
        float t  = xb[oc*VP + v] + (yf - mm)*sc + be;
        out28[v] = (t >= 0.f) ? t : LEAK*t;
    }
    float4* dst = (float4*)&g_buf2[n*CTV28 + oc*TV28 + (t0+tq)*VP];
#pragma unroll
    for (int j = 0; j < 7; j++)
        dst[j] = make_float4(out28[4*j], out28[4*j+1], out28[4*j+2], out28[4*j+3]);
}

// ---------------------------------------------------------------------------
// K4: z = BN(tconv3(y3) + b_t); out = lrelu(y3 + z) -> d_out (stride 27)
// ---------------------------------------------------------------------------
#define K4_SMEM_FLOATS (3*64*64 + 64*6*VP)
__global__ __launch_bounds__(256) void k4_tconv(
    const float* __restrict__ Wt, const float* __restrict__ bt,
    const float* __restrict__ gt, const float* __restrict__ bet,
    const float* __restrict__ mt, const float* __restrict__ vt,
    float* __restrict__ out) {
    extern __shared__ float sm[];
    float* sW = sm;            // [kt][c][oc]
    float* sY = sm + 12288;    // [c][tt=6][VP]
    int n = blockIdx.y, t0 = blockIdx.x*4;
    int tid = threadIdx.y*64 + threadIdx.x;
    for (int i = tid; i < 12288; i += 256) {
        int o = i&63; int ii = (i>>6)&63; int kt = i>>12;
        sW[i] = Wt[(o*64 + ii)*3 + kt];
    }
    for (int i = tid; i < 2688; i += 256) {
        int j = i%7; int tt = (i/7)%6; int c = i/42;
        int t = t0 - 1 + tt;
        float4 val = make_float4(0.f,0.f,0.f,0.f);
        if (t >= 0 && t < TTT)
            val = ((const float4*)&g_buf2[n*CTV28 + c*TV28 + t*VP])[j];
        ((float4*)&sY[(c*6+tt)*VP])[j] = val;
    }
    __syncthreads();

    int oc = threadIdx.x, tq = threadIdx.y;
    u64 b2 = bcast2(bt[oc]);
    u64 acc[14];
#pragma unroll
    for (int j = 0; j < 14; j++) acc[j] = b2;
#pragma unroll
    for (int dt = 0; dt < 3; dt++) {
        for (int c = 0; c < 64; c++) {
            u64 w2 = bcast2(sW[(dt*64+c)*64 + oc]);
            const ulonglong2* y2p = (const ulonglong2*)&sY[(c*6 + tq + dt)*VP];
#pragma unroll
            for (int j = 0; j < 7; j++) {
                ulonglong2 q = y2p[j];
                acc[2*j]   = ffma2(w2, q.x, acc[2*j]);
                acc[2*j+1] = ffma2(w2, q.y, acc[2*j+1]);
            }
        }
    }
    float sc = gt[oc]*rsqrtf(vt[oc]+EPSB);
    float mm = mt[oc], be = bet[oc];
    float accf[28];
#pragma unroll
    for (int j = 0; j < 14; j++) { float2 p = unpk(acc[j]); accf[2*j] = p.x; accf[2*j+1] = p.y; }
    float* dst = &out[n*CTV + oc*TVC + (t0+tq)*27];
    const float* yc = &sY[(oc*6 + tq + 1)*VP];
#pragma unroll
    for (int v = 0; v < 27; v++) {
        float z = (accf[v] - mm)*sc + be;
        float r = yc[v] + z;
        dst[v] = (r >= 0.f) ? r : LEAK*r;
    }
}

// ---------------------------------------------------------------------------
extern "C" void kernel_launch(void* const* d_in, const int* in_sizes, int n_in,
                              void* d_out, int out_size) {
    const float* x      = (const float*)d_in[0];
    const float* pe     = (const float*)d_in[1];
    const float* W_in   = (const float*)d_in[2];
    const float* b_in   = (const float*)d_in[3];
    const float* alphas = (const float*)d_in[4];
    const float* att0   = (const float*)d_in[5];
    const float* W_out  = (const float*)d_in[6];
    const float* b_out  = (const float*)d_in[7];
    const float* g_out  = (const float*)d_in[8];
    const float* be_out = (const float*)d_in[9];
    const float* m_out  = (const float*)d_in[10];
    const float* v_out  = (const float*)d_in[11];
    const float* W_ff   = (const float*)d_in[12];
    const float* b_ff   = (const float*)d_in[13];
    const float* g_ff   = (const float*)d_in[14];
    const float* be_ff  = (const float*)d_in[15];
    const float* m_ff   = (const float*)d_in[16];
    const float* v_ff   = (const float*)d_in[17];
    const float* W_t    = (const float*)d_in[18];
    const float* b_t    = (const float*)d_in[19];
    const float* g_t    = (const float*)d_in[20];
    const float* be_t   = (const float*)d_in[21];
    const float* m_t    = (const float*)d_in[22];
    const float* v_t    = (const float*)d_in[23];
    float* out = (float*)d_out;

    cudaFuncSetAttribute(k3a, cudaFuncAttributeMaxDynamicSharedMemorySize,
                         K3A_SMEM_FLOATS*4);
    cudaFuncSetAttribute(k3b, cudaFuncAttributeMaxDynamicSharedMemorySize,
                         K3B_SMEM_FLOATS*4);
    cudaFuncSetAttribute(k4_tconv, cudaFuncAttributeMaxDynamicSharedMemorySize,
                         K4_SMEM_FLOATS*4);

    dim3 blk(64, 4);
    k1_qk<<<dim3(100, 32), blk>>>(x, pe, W_in, b_in);
    k2_part<<<dim3(KSP, 2, 32), 96>>>();
    k2_fin<<<(NN*SSS*729 + 255)/256, 256>>>(alphas, att0);
    k3a<<<dim3(100, 32), blk, K3A_SMEM_FLOATS*4>>>(
        x, W_out, b_out, g_out, be_out, m_out, v_out);
    k3b<<<dim3(100, 32), blk, K3B_SMEM_FLOATS*4>>>(
        x, W_ff, b_ff, g_ff, be_ff, m_ff, v_ff);
    k4_tconv<<<dim3(100, 32), blk, K4_SMEM_FLOATS*4>>>(
        W_t, b_t, g_t, be_t, m_t, v_t, out);
}